// round 2
// baseline (speedup 1.0000x reference)
#include <cuda_runtime.h>

// Scratch for per-(b,n) log-det values (deterministic reduction in kernel 2).
__device__ float g_ldj[1 << 20];

// Robust permute parse: harness may deliver int64 (reference dtype) or
// downcast to int32. Detect by checking the int32 view is a permutation
// of {0,1,2}; otherwise fall back to int64 view.
__device__ __forceinline__ void get_perm(const void* pptr, int& p0, int& p1, int& p2)
{
    const int* pi = (const int*)pptr;
    int a = pi[0], b = pi[1], c = pi[2];
    bool ok = ((unsigned)a < 3u) && ((unsigned)b < 3u) && ((unsigned)c < 3u) &&
              (((1 << a) | (1 << b) | (1 << c)) == 7);
    if (!ok) {
        const long long* pl = (const long long*)pptr;
        a = (int)pl[0]; b = (int)pl[1]; c = (int)pl[2];
    }
    p0 = a; p1 = b; p2 = c;
}

__global__ void mobius_kernel(const float* __restrict__ rot,
                              const float* __restrict__ cond,
                              const void* __restrict__ perm,
                              float* __restrict__ out_rot,
                              int BN)
{
    int warp_id = (int)((blockIdx.x * (unsigned)blockDim.x + threadIdx.x) >> 5);
    int lane = threadIdx.x & 31;
    if (warp_id >= BN) return;

    int p0, p1, p2;
    get_perm(perm, p0, p1, p2);

    const float* R = rot + (size_t)warp_id * 9;
    float x0 = R[0 * 3 + p0], x1 = R[1 * 3 + p0], x2 = R[2 * 3 + p0];
    float y0 = R[0 * 3 + p1], y1 = R[1 * 3 + p1], y2 = R[2 * 3 + p1];

    // Per-n precompute (redundant in every lane; broadcast loads, cheap)
    float xx = x0 * x0 + x1 * x1 + x2 * x2;
    float invxn = rsqrtf(xx);
    float r0 = -x0 * invxn, r1 = -x1 * invxn, r2 = -x2 * invxn;

    // v = normalize(cross(y, r))
    float v0 = y1 * r2 - y2 * r1;
    float v1 = y2 * r0 - y0 * r2;
    float v2 = y0 * r1 - y1 * r0;
    float invvn = rsqrtf(v0 * v0 + v1 * v1 + v2 * v2);
    v0 *= invvn; v1 *= invvn; v2 *= invvn;

    float yy = y0 * y0 + y1 * y1 + y2 * y2;
    float xy = x0 * y0 + x1 * y1 + x2 * y2;
    float xv = x0 * v0 + x1 * v1 + x2 * v2;
    float xr = x0 * r0 + x1 * r1 + x2 * r2;
    float yr = y0 * r0 + y1 * r1 + y2 * r2;
    float yv = y0 * v0 + y1 * v1 + y2 * v2;   // ~0 but kept for fidelity

    const float* C = cond + (size_t)warp_id * 256;

    float accA = 0.0f, accD = 0.0f, accS = 0.0f;

    #pragma unroll
    for (int half = 0; half < 2; ++half) {
        int k = lane + half * 32;
        float wt = C[k];                       // coalesced 128B line
        const float* W = C + 64 + 3 * k;       // coalesced across lanes
        float w0 = W[0], w1 = W[1], w2c = W[2];

        // Dots with raw w; projection/scaling folded into scalars.
        float a  = y0 * w0 + y1 * w1 + y2 * w2c;
        float ww = w0 * w0 + w1 * w1 + w2c * w2c;
        float xw = x0 * w0 + x1 * w1 + x2 * w2c;
        float vw = v0 * w0 + v1 * w1 + v2 * w2c;
        float rw = r0 * w0 + r1 * w1 + r2 * w2c;

        // ||w - a*y||^2 = ww - 2a^2 + a^2*yy
        float wpn2 = ww - a * a * (2.0f - yy);
        wpn2 = fmaxf(wpn2, 1e-30f);
        float q  = rsqrtf(wpn2);
        float sq = wpn2 * q;                       // sqrt(wpn2)
        float s  = __fdividef(0.7f, 1.0f + sq);    // scale factor
        float w2n = s * s * wpn2;                  // ||w_scaled||^2

        float sxw = s * (xw - a * xy);             // x . w_scaled
        float svw = s * (vw - a * yv);             // v . w_scaled
        float srw = s * (rw - a * yr);             // r . w_scaled

        float n2 = xx - 2.0f * sxw + w2n;          // ||x - w||^2
        float factor = __fdividef(1.0f - w2n, n2);

        // h = factor*(x - w) - w ;  h.v , h.r
        float hv = factor * (xv - svw) - svw;
        float hr = factor * (xr - srw) - srw;
        float ang = atan2f(hv, hr);
        if (ang < 0.0f) ang += 6.28318530717958647692f;

        // softplus (numerically stable)
        float sp = fmaxf(wt, 0.0f) + log1pf(__expf(-fabsf(wt)));

        accA = fmaf(sp, ang, accA);
        accD = fmaf(sp, factor, accD);   // ||dh_dtheta|| == factor (Householder)
        accS += sp;
    }

    // Warp butterfly reduction
    #pragma unroll
    for (int off = 16; off; off >>= 1) {
        accA += __shfl_xor_sync(0xffffffffu, accA, off);
        accD += __shfl_xor_sync(0xffffffffu, accD, off);
        accS += __shfl_xor_sync(0xffffffffu, accS, off);
    }

    float invS = __fdividef(1.0f, accS);
    float ang = accA * invS;
    float dtx = accD * invS;
    float ldj = logf(dtx);

    float sa, ca;
    __sincosf(ang, &sa, &ca);
    float t0 = r0 * ca + v0 * sa;
    float t1 = r1 * ca + v1 * sa;
    float t2 = r2 * ca + v2 * sa;

    int d = p1 - p0;
    float z0, z1, z2;
    if (d == 1 || d == -2) {           // tz = cross(tx, y)
        z0 = t1 * y2 - t2 * y1;
        z1 = t2 * y0 - t0 * y2;
        z2 = t0 * y1 - t1 * y0;
    } else {                           // tz = cross(y, tx)
        z0 = y1 * t2 - y2 * t1;
        z1 = y2 * t0 - y0 * t2;
        z2 = y0 * t1 - y1 * t0;
    }
    float invzn = rsqrtf(z0 * z0 + z1 * z1 + z2 * z2);
    z0 *= invzn; z1 *= invzn; z2 *= invzn;

    if (lane == 0) g_ldj[warp_id] = ldj;

    if (lane < 9) {
        int i = lane / 3;   // row
        int j = lane % 3;   // col
        float ti = (i == 0) ? t0 : ((i == 1) ? t1 : t2);
        float yi = (i == 0) ? y0 : ((i == 1) ? y1 : y2);
        float zi = (i == 0) ? z0 : ((i == 1) ? z1 : z2);
        float val = (j == p0) ? ti : ((j == p1) ? yi : zi);
        out_rot[(size_t)warp_id * 9 + lane] = val;
    }
}

__global__ void ldj_reduce_kernel(float* __restrict__ out, int B, int N, int offset)
{
    int b = blockIdx.x * blockDim.x + threadIdx.x;
    if (b >= B) return;
    float sum = 0.0f;
    for (int n = 0; n < N; ++n)
        sum += g_ldj[b * N + n];
    out[offset + b] = sum;
}

extern "C" void kernel_launch(void* const* d_in, const int* in_sizes, int n_in,
                              void* d_out, int out_size)
{
    const float* rot = (const float*)d_in[0];
    const float* cond = (const float*)d_in[1];
    const void* perm = d_in[2];
    float* out = (float*)d_out;

    int BN = in_sizes[0] / 9;            // 86016
    int B  = out_size - in_sizes[0];     // 4096 (out = BN*9 trotation + B ldj)
    int N  = BN / B;                     // 21

    int threads = 256;                    // 8 warps/block, 1 warp per (b,n)
    int blocks = (BN * 32 + threads - 1) / threads;
    mobius_kernel<<<blocks, threads>>>(rot, cond, perm, out, BN);

    ldj_reduce_kernel<<<(B + 255) / 256, 256>>>(out, B, N, in_sizes[0]);
}

// round 4
// speedup vs baseline: 1.4121x; 1.4121x over previous
#include <cuda_runtime.h>

__device__ float g_ldj[1 << 20];

#define ITEMS_PER_BLOCK 64
#define SM_STRIDE 260   // 256 floats of cond + 4 pad (260 % 32 == 4 -> conflict-free across items)

// Robust permute parse: int32 view if it's a valid permutation of {0,1,2}, else int64.
__device__ __forceinline__ void get_perm(const void* pptr, int& p0, int& p1, int& p2)
{
    const int* pi = (const int*)pptr;
    int a = pi[0], b = pi[1], c = pi[2];
    bool ok = ((unsigned)a < 3u) && ((unsigned)b < 3u) && ((unsigned)c < 3u) &&
              (((1 << a) | (1 << b) | (1 << c)) == 7);
    if (!ok) {
        const long long* pl = (const long long*)pptr;
        a = (int)pl[0]; b = (int)pl[1]; c = (int)pl[2];
    }
    p0 = a; p1 = b; p2 = c;
}

// atan(t) for t >= 0, cephes-style two-stage range reduction, max err ~2e-7 rad.
__device__ __forceinline__ float atan_pos(float t)
{
    float y0, x;
    if (t > 2.414213562373095f)       { y0 = 1.5707963267948966f; x = __fdividef(-1.0f, t); }
    else if (t > 0.4142135623730950f) { y0 = 0.7853981633974483f; x = __fdividef(t - 1.0f, t + 1.0f); }
    else                              { y0 = 0.0f;                x = t; }
    float z = x * x;
    float p = ((8.05374449538e-2f * z - 1.38776856032e-1f) * z + 1.99777106478e-1f) * z
              - 3.33329491539e-1f;
    return y0 + fmaf(p * z, x, x);
}

// angle(hv, hr) in [0, 2*pi): equivalent to atan2 + (+2pi if negative) fixup.
__device__ __forceinline__ float angle02pi(float hv, float hr)
{
    float ax = fabsf(hr), ay = fabsf(hv);
    float r = atan_pos(__fdividef(ay, ax));
    if (hr < 0.0f) r = 3.14159265358979323846f - r;
    if (hv < 0.0f) r = 6.28318530717958647692f - r;
    return r;
}

__global__ void __launch_bounds__(256)
mobius_kernel(const float* __restrict__ rot,
              const float* __restrict__ cond,
              const void* __restrict__ perm,
              float* __restrict__ out_rot,
              int BN)
{
    extern __shared__ float sm[];
    const int tid = threadIdx.x;
    const int block_item0 = blockIdx.x * ITEMS_PER_BLOCK;

    // ---- Phase 0: stage 64 items x 1KB of conditions into smem (coalesced float4) ----
    {
        const float4* src = (const float4*)(cond + (size_t)block_item0 * 256);
        #pragma unroll
        for (int it = 0; it < 16; ++it) {
            int gi = it * 256 + tid;         // float4 index within the block's 64KB chunk
            int li = gi >> 6;                // local item
            int f  = gi & 63;                // float4 within item
            if (block_item0 + li < BN) {
                float4 vdat = src[gi];
                *(float4*)&sm[li * SM_STRIDE + 4 * f] = vdat;
            }
        }
    }
    __syncthreads();

    const int li   = tid >> 2;               // local item 0..63
    const int q    = tid & 3;                // lane within 4-lane group
    const int item = block_item0 + li;
    if (item >= BN) return;

    int p0, p1, p2;
    get_perm(perm, p0, p1, p2);

    // ---- Per-item precompute (x4 redundant within group; cheap) ----
    const float* R = rot + (size_t)item * 9;
    float x0 = R[0 * 3 + p0], x1 = R[1 * 3 + p0], x2 = R[2 * 3 + p0];
    float y0 = R[0 * 3 + p1], y1 = R[1 * 3 + p1], y2 = R[2 * 3 + p1];

    float xx = x0 * x0 + x1 * x1 + x2 * x2;
    float invxn = rsqrtf(xx);
    float r0 = -x0 * invxn, r1 = -x1 * invxn, r2 = -x2 * invxn;

    float v0 = y1 * r2 - y2 * r1;
    float v1 = y2 * r0 - y0 * r2;
    float v2 = y0 * r1 - y1 * r0;
    float invvn = rsqrtf(v0 * v0 + v1 * v1 + v2 * v2);
    v0 *= invvn; v1 *= invvn; v2 *= invvn;

    float yy = y0 * y0 + y1 * y1 + y2 * y2;
    float xy = x0 * y0 + x1 * y1 + x2 * y2;
    float xv = x0 * v0 + x1 * v1 + x2 * v2;
    float xr = x0 * r0 + x1 * r1 + x2 * r2;
    float yr = y0 * r0 + y1 * r1 + y2 * r2;
    float yv = y0 * v0 + y1 * v1 + y2 * v2;

    const float* S = sm + li * SM_STRIDE;

    float accA = 0.0f, accD = 0.0f, accS = 0.0f;

    #pragma unroll 4
    for (int j = 0; j < 16; ++j) {
        int k = j * 4 + q;
        float wt  = S[k];
        float w0  = S[64 + 3 * k];
        float w1  = S[65 + 3 * k];
        float w2c = S[66 + 3 * k];

        float a  = y0 * w0 + y1 * w1 + y2 * w2c;
        float ww = w0 * w0 + w1 * w1 + w2c * w2c;
        float xw = x0 * w0 + x1 * w1 + x2 * w2c;
        float vw = v0 * w0 + v1 * w1 + v2 * w2c;
        float rw = r0 * w0 + r1 * w1 + r2 * w2c;

        float wpn2 = ww - a * a * (2.0f - yy);     // ||w - a*y||^2
        wpn2 = fmaxf(wpn2, 1e-30f);
        float iq  = rsqrtf(wpn2);
        float sq  = wpn2 * iq;                     // sqrt
        float s   = __fdividef(0.7f, 1.0f + sq);
        float w2n = s * s * wpn2;

        float sxw = s * (xw - a * xy);
        float svw = s * (vw - a * yv);
        float srw = s * (rw - a * yr);

        float n2 = xx - 2.0f * sxw + w2n;
        float factor = __fdividef(1.0f - w2n, n2);

        float hv = factor * (xv - svw) - svw;
        float hr = factor * (xr - srw) - srw;
        float ang = angle02pi(hv, hr);

        // softplus: max(x,0) + log(1 + exp(-|x|)) with fast intrinsics
        float sp = fmaxf(wt, 0.0f) + __logf(1.0f + __expf(-fabsf(wt)));

        accA = fmaf(sp, ang, accA);
        accD = fmaf(sp, factor, accD);
        accS += sp;
    }

    // ---- 4-lane butterfly reduction (groups are lane-aligned) ----
    #pragma unroll
    for (int off = 1; off < 4; off <<= 1) {
        accA += __shfl_xor_sync(0xffffffffu, accA, off);
        accD += __shfl_xor_sync(0xffffffffu, accD, off);
        accS += __shfl_xor_sync(0xffffffffu, accS, off);
    }

    float invS = __fdividef(1.0f, accS);
    float ang = accA * invS;
    float dtx = accD * invS;
    float ldj = __logf(dtx);

    float sa, ca;
    __sincosf(ang, &sa, &ca);
    float t0 = r0 * ca + v0 * sa;
    float t1 = r1 * ca + v1 * sa;
    float t2 = r2 * ca + v2 * sa;

    int d = p1 - p0;
    float z0, z1, z2;
    if (d == 1 || d == -2) {           // tz = cross(tx, y)
        z0 = t1 * y2 - t2 * y1;
        z1 = t2 * y0 - t0 * y2;
        z2 = t0 * y1 - t1 * y0;
    } else {                           // tz = cross(y, tx)
        z0 = y1 * t2 - y2 * t1;
        z1 = y2 * t0 - y0 * t2;
        z2 = y0 * t1 - y1 * t0;
    }
    float invzn = rsqrtf(z0 * z0 + z1 * z1 + z2 * z2);
    z0 *= invzn; z1 *= invzn; z2 *= invzn;

    if (q == 0) g_ldj[item] = ldj;

    #pragma unroll
    for (int idx = q; idx < 9; idx += 4) {
        int i = idx / 3, jj = idx % 3;
        float ti = (i == 0) ? t0 : ((i == 1) ? t1 : t2);
        float yi = (i == 0) ? y0 : ((i == 1) ? y1 : y2);
        float zi = (i == 0) ? z0 : ((i == 1) ? z1 : z2);
        float val = (jj == p0) ? ti : ((jj == p1) ? yi : zi);
        out_rot[(size_t)item * 9 + idx] = val;
    }
}

// Warp per batch element: coalesced 21-float read + butterfly reduce.
__global__ void ldj_reduce_kernel(float* __restrict__ out, int B, int N, int offset)
{
    int warp = (int)((blockIdx.x * (unsigned)blockDim.x + threadIdx.x) >> 5);
    int lane = threadIdx.x & 31;
    if (warp >= B) return;
    float v = (lane < N) ? g_ldj[warp * N + lane] : 0.0f;
    #pragma unroll
    for (int off = 16; off; off >>= 1)
        v += __shfl_xor_sync(0xffffffffu, v, off);
    if (lane == 0) out[offset + warp] = v;
}

extern "C" void kernel_launch(void* const* d_in, const int* in_sizes, int n_in,
                              void* d_out, int out_size)
{
    const float* rot = (const float*)d_in[0];
    const float* cond = (const float*)d_in[1];
    const void* perm = d_in[2];
    float* out = (float*)d_out;

    int BN = in_sizes[0] / 9;            // 86016
    int B  = out_size - in_sizes[0];     // 4096
    int N  = BN / B;                     // 21

    const int smem_bytes = ITEMS_PER_BLOCK * SM_STRIDE * sizeof(float);  // 66560
    cudaFuncSetAttribute(mobius_kernel, cudaFuncAttributeMaxDynamicSharedMemorySize, smem_bytes);

    int blocks = (BN + ITEMS_PER_BLOCK - 1) / ITEMS_PER_BLOCK;           // 1344
    mobius_kernel<<<blocks, 256, smem_bytes>>>(rot, cond, perm, out, BN);

    int rblocks = (B * 32 + 255) / 256;                                  // 512
    ldj_reduce_kernel<<<rblocks, 256>>>(out, B, N, in_sizes[0]);
}